// round 13
// baseline (speedup 1.0000x reference)
#include <cuda_runtime.h>
#include <cuda_bf16.h>

// Yolov1 loss — persistent kernel, 2-stage cp.async ring with SPARSE chunk
// loading: grid==0 cells (~50%) only need their 2 conf floats, so their other
// chunks are never fetched. grid prefetched a tile ahead -> ballot obj-mask ->
// per-16B-chunk cp.async predicate. tbox/tcls loads predicated on grid==1.
// B=16384, cells = 802816 = 25088 tiles of 32 cells (3840 B full tile).
// 444 blocks * 8 warps = 3552 streams; sid = wid*444 + blockIdx.x;
// stream sid: start = sid*7 + min(sid,224), cnt = 7 + (sid<224) (contiguous run).
// Cell layout: [0:2) conf, [2:10) boxes (NB,4), [10:30) class logits.

#define NBLOCKS  444
#define NTHREADS 256
#define NSTREAMS (NBLOCKS * 8)   // 3552
#define NTILES   25088
#define NEXTRA   (NTILES - NSTREAMS * 7)   // 224

__device__ float g_partials[NBLOCKS];
__device__ unsigned int g_done = 0;   // atomicInc mod NBLOCKS -> self-resetting

__device__ __forceinline__ float fsig(float x) {
    float t;
    asm("tanh.approx.f32 %0, %1;" : "=f"(t) : "f"(x * 0.5f));
    return fmaf(t, 0.5f, 0.5f);
}
__device__ __forceinline__ float fsqrt_a(float x) {
    float r;
    asm("sqrt.approx.f32 %0, %1;" : "=f"(r) : "f"(x));
    return r;
}
__device__ __forceinline__ unsigned int smem_u32(const void* p) {
    return (unsigned int)__cvta_generic_to_shared(p);
}

// Full obj-cell loss. p = 30 floats in smem; targets in registers.
__device__ __forceinline__ float obj_loss_f(const float* __restrict__ p, int t,
                                            float4 tb, int tc)
{
    const int s = t % 49;
    const float xg = (float)(s % 7);
    const float yg = (float)(s / 7);
    const float inv7 = 1.0f / 7.0f;
    const float tox = tb.x, toy = tb.y, tw = tb.z, th = tb.w;

    const float conf0 = fsig(p[0]);
    const float conf1 = fsig(p[1]);
    float pb[2][4];
    #pragma unroll
    for (int nb = 0; nb < 2; nb++)
        #pragma unroll
        for (int k = 0; k < 4; k++)
            pb[nb][k] = fsig(p[2 + nb * 4 + k]);

    float esum = 0.0f, et = 0.0f;
    #pragma unroll
    for (int j = 0; j < 20; j++) {
        const float e = __expf(p[10 + j]);
        esum += e;
        if (j == tc) et = e;
    }
    const float cls_t = __fdividef(et, esum);

    const float tcx = (xg + tox) * inv7;
    const float tcy = (yg + toy) * inv7;
    float iou[2];
    #pragma unroll
    for (int nb = 0; nb < 2; nb++) {
        const float pcx = (xg + pb[nb][0]) * inv7;
        const float pcy = (yg + pb[nb][1]) * inv7;
        const float pw = pb[nb][2], ph = pb[nb][3];
        const float tb_ = fminf(tcx + tw * 0.5f, pcx + pw * 0.5f)
                        - fmaxf(tcx - tw * 0.5f, pcx - pw * 0.5f);
        const float lr_ = fminf(tcy + th * 0.5f, pcy + ph * 0.5f)
                        - fmaxf(tcy - th * 0.5f, pcy - ph * 0.5f);
        const float inter = (tb_ < 0.0f || lr_ < 0.0f) ? 0.0f : tb_ * lr_;
        iou[nb] = __fdividef(inter, tw * th + pw * ph - inter);
    }

    const int best = (iou[1] > iou[0]) ? 1 : 0;
    const float iou_b  = iou[best];
    const float conf_b = best ? conf1 : conf0;

    const float d0 = pb[best][0] - tox;
    const float d1 = pb[best][1] - toy;
    const float d2 = fsqrt_a(pb[best][2]) - fsqrt_a(tw);
    const float d3 = fsqrt_a(pb[best][3]) - fsqrt_a(th);
    const float coord = d0 * d0 + d1 * d1 + d2 * d2 + d3 * d3;

    const float dc = conf_b - iou_b;
    const float dl = 1.0f - cls_t;
    return 5.0f * coord + dc * dc + dl * dl;
}

// Issue cp.async only for needed 16B chunks of a tile. mask = obj bits (cell 0..31).
// Chunk k covers cells c0=16k/120 .. c1=(16k+15)/120. Needed iff an obj cell
// touches it, a cell boundary is inside it (next cell's conf starts there), or
// it is the conf chunk of its (even) cell: 16k mod 120 < 8.
__device__ __forceinline__ void issue_tile_sparse(float* __restrict__ dst,
                                                  const float4* __restrict__ pred4,
                                                  int tile, int lane,
                                                  unsigned int mask)
{
    const float4* src = pred4 + (long)tile * 240;
    #pragma unroll
    for (int i = 0; i < 8; i++) {
        const int k = lane + i * 32;
        if (k < 240) {
            const int b  = k * 16;
            const int c0 = b / 120;
            const int c1 = (b + 15) / 120;
            const bool need = (((mask >> c0) | (mask >> c1)) & 1u)
                            | (c1 != c0)
                            | ((b - c0 * 120) < 8);
            if (need) {
                const unsigned int da = smem_u32(dst + k * 4);
                asm volatile("cp.async.cg.shared.global [%0], [%1], 16;"
                             :: "r"(da), "l"(src + k));
            }
        }
    }
}

__global__ __launch_bounds__(NTHREADS, 3)
void yolo_loss_kernel(const float* __restrict__ pred,
                      const int*   __restrict__ grid,
                      const float* __restrict__ tbox,
                      const int*   __restrict__ tcls,
                      float* __restrict__ out)
{
    // 2 stages * 8 warps * 960 floats = 61440 B
    __shared__ float sp[2 * 8 * 960];

    const int lane = threadIdx.x & 31;
    const int wid  = threadIdx.x >> 5;

    // Contiguous runs; remainder on warp 0 of blocks 0..223.
    const int sid   = wid * NBLOCKS + blockIdx.x;
    const int start = sid * 7 + min(sid, NEXTRA);
    const int cnt   = 7 + (sid < NEXTRA ? 1 : 0);

    float* const s0 = sp + wid * 960;
    float* const s1 = sp + (8 + wid) * 960;
    const float4* const tbox4 = reinterpret_cast<const float4*>(tbox);
    const float4* const pred4 = reinterpret_cast<const float4*>(pred);

    // ---- prologue ----
    // tile 0: grid -> mask -> sparse issue; predicated targets.
    int g = __ldg(grid + start * 32 + lane);
    unsigned int mask = __ballot_sync(0xffffffffu, g == 1);
    issue_tile_sparse(s0, pred4, start, lane, mask);
    asm volatile("cp.async.commit_group;");

    float4 tb = {}; int tc = 0;
    if (g == 1) {
        tb = __ldg(tbox4 + start * 32 + lane);
        tc = __ldg(tcls + start * 32 + lane);
    }
    // grid of tile 1 (mask computed at first loop iteration)
    int gn = 0;
    if (cnt > 1) gn = __ldg(grid + (start + 1) * 32 + lane);

    float v = 0.0f;
    int stage = 0;
    float4 tbn; int tcn;

    for (int it = 0; ; it++) {
        const bool validn = (it + 1 < cnt);
        const int tn = start + it + 1;

        // issue next tile sparsely (gn loaded a full iteration ago)
        if (validn) {
            const unsigned int maskn = __ballot_sync(0xffffffffu, gn == 1);
            issue_tile_sparse(stage ? s0 : s1, pred4, tn, lane, maskn);
        }
        asm volatile("cp.async.commit_group;");   // uniform group count

        // predicated target prefetch for tile it+1; grid for tile it+2
        tbn = make_float4(0.f, 0.f, 0.f, 0.f); tcn = 0;
        if (validn && gn == 1) {
            tbn = __ldg(tbox4 + tn * 32 + lane);
            tcn = __ldg(tcls + tn * 32 + lane);
        }
        int gnn = 0;
        if (it + 2 < cnt) gnn = __ldg(grid + (tn + 1) * 32 + lane);

        if (validn) asm volatile("cp.async.wait_group 1;");
        else        asm volatile("cp.async.wait_group 0;");
        __syncwarp();

        // compute tile it — noobj lanes touch ONLY their conf chunk
        {
            const float* p = (stage ? s1 : s0) + lane * 30;
            if (g == 1) {
                v += obj_loss_f(p, (start + it) * 32 + lane, tb, tc);
            } else {
                const float c0f = fsig(p[0]);
                const float c1f = fsig(p[1]);
                v += 0.5f * (c0f * c0f + c1f * c1f);
            }
        }
        __syncwarp();

        if (!validn) break;
        tb = tbn; g = gn; tc = tcn; gn = gnn;
        stage ^= 1;
    }

    // ---- block reduction -> g_partials[blockIdx.x] ----
    #pragma unroll
    for (int o = 16; o; o >>= 1) v += __shfl_down_sync(0xffffffffu, v, o);
    __shared__ float wsum[NTHREADS / 32];
    __shared__ bool s_last;
    if (lane == 0) wsum[wid] = v;
    __syncthreads();
    if (threadIdx.x < NTHREADS / 32) {
        v = wsum[threadIdx.x];
        #pragma unroll
        for (int o = NTHREADS / 64; o; o >>= 1) v += __shfl_down_sync(0xffu, v, o);
        if (threadIdx.x == 0) {
            g_partials[blockIdx.x] = v;
            __threadfence();
            unsigned int prev = atomicInc(&g_done, NBLOCKS - 1);
            s_last = (prev == NBLOCKS - 1);
        }
    }
    __syncthreads();

    // ---- last-arriving block: deterministic final reduction ----
    if (s_last) {
        double acc = 0.0;
        for (int i = threadIdx.x; i < NBLOCKS; i += NTHREADS)
            acc += (double)g_partials[i];
        #pragma unroll
        for (int o = 16; o; o >>= 1) acc += __shfl_down_sync(0xffffffffu, acc, o);
        __shared__ double ws[NTHREADS / 32];
        if (lane == 0) ws[wid] = acc;
        __syncthreads();
        if (threadIdx.x == 0) {
            double sum = 0.0;
            #pragma unroll
            for (int i = 0; i < NTHREADS / 32; i++) sum += ws[i];
            out[0] = (float)(sum / 16384.0);
        }
    }
}

extern "C" void kernel_launch(void* const* d_in, const int* in_sizes, int n_in,
                              void* d_out, int out_size)
{
    const float* pred = (const float*)d_in[0];   // (B, 1470) f32
    const int*   grid = (const int*)  d_in[1];   // (B, 7, 7) i32
    const float* tbox = (const float*)d_in[2];   // (B, 7, 7, 4) f32
    const int*   tcls = (const int*)  d_in[3];   // (B, 7, 7) i32
    float* out = (float*)d_out;

    yolo_loss_kernel<<<NBLOCKS, NTHREADS>>>(pred, grid, tbox, tcls, out);
}